// round 13
// baseline (speedup 1.0000x reference)
#include <cuda_runtime.h>
#include <cuda_bf16.h>

// Problem constants (fixed by the dataset)
#define BATCH 8
#define CH    256
#define NPTS  65536
#define HID   256
#define OUTC  8
#define TOPK  512

#define CAP   8192
#define BAND  32       // 16-bit buckets below approx threshold (fp8 error model)

// Scratch (no cudaMalloc). Zero-init at load; consumers self-reset for replay.
__device__ float g_score[BATCH * NPTS];
__device__ __align__(16) unsigned int g_hist16[BATCH * 65536];
__device__ int g_candidx[BATCH * CAP];
__device__ unsigned long long g_cand[BATCH * CAP];
__device__ __align__(16) float g_rows[BATCH * CAP * OUTC];   // exact 8-ch rows per candidate
__device__ int g_cnt[BATCH];
__device__ int g_thresh[BATCH];
__device__ __align__(16) unsigned char g_w1f8[HID * CH];     // W1^T e4m3 [n][k]

__device__ __forceinline__ unsigned int fkey(float f) {
    unsigned int u = __float_as_uint(f);
    return (u & 0x80000000u) ? ~u : (u | 0x80000000u);
}

// ---------------- helpers ----------------
__device__ __forceinline__ void cp16(unsigned dst, const void* src) {
    asm volatile("cp.async.cg.shared.global [%0], [%1], 16;" :: "r"(dst), "l"(src));
}
__device__ __forceinline__ void cp_commit() { asm volatile("cp.async.commit_group;"); }
__device__ __forceinline__ void cp_wait0() { asm volatile("cp.async.wait_group 0;"); }

// two floats -> packed e4m3x2 in low 16 bits (lo byte = a, hi byte = b)
__device__ __forceinline__ unsigned short f2e4m3x2(float a, float b) {
    unsigned short r;
    asm("cvt.rn.satfinite.e4m3x2.f32 %0, %1, %2;" : "=h"(r) : "f"(b), "f"(a));
    return r;
}

#define LDSM4(r0, r1, r2, r3, addr)                                           \
    asm volatile("ldmatrix.sync.aligned.m8n8.x4.shared.b16 "                  \
                 "{%0,%1,%2,%3}, [%4];"                                       \
                 : "=r"(r0), "=r"(r1), "=r"(r2), "=r"(r3) : "r"(addr))

#define MMA_E4M3(c0, c1, c2, c3, a0, a1, a2, a3, b0, b1)                      \
    asm volatile("mma.sync.aligned.m16n8k32.row.col.f32.e4m3.e4m3.f32 "       \
                 "{%0,%1,%2,%3}, {%4,%5,%6,%7}, {%8,%9}, {%0,%1,%2,%3};"      \
                 : "+f"(c0), "+f"(c1), "+f"(c2), "+f"(c3)                     \
                 : "r"(a0), "r"(a1), "r"(a2), "r"(a3), "r"(b0), "r"(b1))

// ================= W1 -> e4m3 [n][k] (transpose + convert) ===================
__global__ void w1f8_kernel(const float* __restrict__ W1) {
    int i = blockIdx.x * 1024 + threadIdx.x;   // i = k*256 + n
    int k = i >> 8, n = i & 255;
    unsigned short p = f2e4m3x2(W1[i], 0.0f);
    g_w1f8[n * 256 + k] = (unsigned char)(p & 0xFF);
}

// ================= Phase A: approx scores via FP8 mma ========================
// Block: 256 points, K=256, HID in 4 reg-chunks of 64 over a fully-resident
// fp8 W1 [256n][272B] + fp8 feat tile A [256pt][272B] (both k-contiguous).
#define BM    256
#define ROWP  272                       // padded row stride bytes (mod 128 = 16)
#define A_SZ  (256 * ROWP)              // 69632
#define ASMEM (2 * A_SZ)                // 139264

__global__ void __launch_bounds__(256)
approx_score_kernel(const float* __restrict__ feat, const float* __restrict__ b1,
                    const float* __restrict__ W2, const float* __restrict__ b2) {
    extern __shared__ char smem[];
    char* fA = smem;                    // A: [pt][k] e4m3
    char* wB = smem + A_SZ;             // B: [n][k] e4m3
    __shared__ float b1s[256];
    __shared__ float w27[256];

    const int tid = threadIdx.x;
    const int b = blockIdx.y;
    const int n0 = blockIdx.x * BM;
    const int lane = tid & 31;
    const int warp = tid >> 5;          // 0..7 -> 32 points each
    const int g = lane >> 2;
    const int tg = lane & 3;
    const int P0 = warp * 32;

    const unsigned fA_u = (unsigned)__cvta_generic_to_shared(fA);
    const unsigned wB_u = (unsigned)__cvta_generic_to_shared(wB);

    // ldmatrix (non-trans) lane address components
    const int aR = lane & 15;                  // row within 16-row m-tile pair
    const int aKo = (lane & 16);               // +16 k-bytes for upper tiles
    const int bR = ((lane & 16) >> 1) + (lane & 7);   // row within 16-n group
    const int bKo = ((lane & 8) << 1);         // +16 k-bytes

    b1s[tid] = b1[tid];
    w27[tid] = W2[tid * OUTC + 7];
    const float b27 = b2[7];

    // stage B: W1 fp8 rows via cp.async (16 chunks/row, 4096 total)
#pragma unroll
    for (int j = 0; j < 16; j++) {
        int idx = j * 256 + tid;        // 0..4095
        int n = idx >> 4;
        int kc = (idx & 15) << 4;
        cp16(wB_u + (unsigned)(n * ROWP + kc), &g_w1f8[n * 256 + kc]);
    }
    cp_commit();

    // stage A: feat [c][pt] fp32 -> fA[pt][c] e4m3 (coalesced LDG.32 gather)
    const float* fbase = feat + (size_t)b * CH * NPTS + n0;
#pragma unroll 4
    for (int it = 0; it < 64; it++) {
        int idx = it * 256 + tid;       // 0..16383
        int pt = idx & 255;
        int kg = idx >> 8;              // 0..63 (4 k per group)
        float f0 = fbase[(size_t)(4 * kg + 0) * NPTS + pt];
        float f1 = fbase[(size_t)(4 * kg + 1) * NPTS + pt];
        float f2 = fbase[(size_t)(4 * kg + 2) * NPTS + pt];
        float f3 = fbase[(size_t)(4 * kg + 3) * NPTS + pt];
        unsigned lo = f2e4m3x2(f0, f1);
        unsigned hi = f2e4m3x2(f2, f3);
        *(unsigned*)(fA + pt * ROWP + 4 * kg) = (hi << 16) | lo;
    }

    cp_wait0();
    __syncthreads();   // A + B fully staged; single sync for the whole GEMM

    float sp[4] = {0.0f, 0.0f, 0.0f, 0.0f};

#pragma unroll 1
    for (int nc = 0; nc < 4; nc++) {
        float c[2][8][4];
#pragma unroll
        for (int mi = 0; mi < 2; mi++)
#pragma unroll
            for (int nt = 0; nt < 8; nt++)
#pragma unroll
                for (int j = 0; j < 4; j++) c[mi][nt][j] = 0.0f;

#pragma unroll
        for (int kt = 0; kt < 8; kt++) {
            const int k0 = kt * 32;
            unsigned a[2][4];
#pragma unroll
            for (int mi = 0; mi < 2; mi++)
                LDSM4(a[mi][0], a[mi][1], a[mi][2], a[mi][3],
                      fA_u + (unsigned)((P0 + mi * 16 + aR) * ROWP + k0 + aKo));
            unsigned bq[4][4];
#pragma unroll
            for (int bi = 0; bi < 4; bi++)
                LDSM4(bq[bi][0], bq[bi][1], bq[bi][2], bq[bi][3],
                      wB_u + (unsigned)((nc * 64 + bi * 16 + bR) * ROWP + k0 + bKo));
#pragma unroll
            for (int mi = 0; mi < 2; mi++)
#pragma unroll
                for (int nt = 0; nt < 8; nt++) {
                    const int bi = nt >> 1, pr = (nt & 1) * 2;
                    MMA_E4M3(c[mi][nt][0], c[mi][nt][1], c[mi][nt][2], c[mi][nt][3],
                             a[mi][0], a[mi][1], a[mi][2], a[mi][3],
                             bq[bi][pr], bq[bi][pr + 1]);
                }
        }

        // relu + b1 + dot W2[:,7] in-register
#pragma unroll
        for (int mi = 0; mi < 2; mi++)
#pragma unroll
            for (int nt = 0; nt < 8; nt++) {
                int col = nc * 64 + nt * 8 + 2 * tg;
                float bb0 = b1s[col], bb1 = b1s[col + 1];
                float w0 = w27[col], w1v = w27[col + 1];
                sp[2 * mi + 0] += fmaxf(c[mi][nt][0] + bb0, 0.0f) * w0 +
                                  fmaxf(c[mi][nt][1] + bb1, 0.0f) * w1v;
                sp[2 * mi + 1] += fmaxf(c[mi][nt][2] + bb0, 0.0f) * w0 +
                                  fmaxf(c[mi][nt][3] + bb1, 0.0f) * w1v;
            }
    }

    // quad-reduce over tg (disjoint hid columns)
#pragma unroll
    for (int j = 0; j < 4; j++) {
        sp[j] += __shfl_xor_sync(0xFFFFFFFFu, sp[j], 1);
        sp[j] += __shfl_xor_sync(0xFFFFFFFFu, sp[j], 2);
    }

    if (tg == 0) {
        const int pts[4] = { P0 + g, P0 + g + 8, P0 + 16 + g, P0 + 24 + g };
#pragma unroll
        for (int j = 0; j < 4; j++) {
            float s = sp[j] + b27;
            g_score[(size_t)b * NPTS + n0 + pts[j]] = s;
            atomicAdd(&g_hist16[(size_t)b * 65536 + (fkey(s) >> 16)], 1u);
        }
    }
}

// ================= Phase B: threshold + band collect =========================
__global__ void thresh_kernel() {
    __shared__ unsigned int sfx[1024];
    const int b = blockIdx.x;
    const int tid = threadIdx.x;
    unsigned int* h = g_hist16 + (size_t)b * 65536;
    const int c0 = tid * 64;

    unsigned int s = 0;
    {
        const uint4* h4 = (const uint4*)(h + c0);
#pragma unroll
        for (int j = 0; j < 16; j++) {
            uint4 v = h4[j];
            s += v.x + v.y + v.z + v.w;
        }
    }
    sfx[tid] = s;
    __syncthreads();
    for (int off = 1; off < 1024; off <<= 1) {
        unsigned int v = sfx[tid];
        unsigned int add = (tid + off < 1024) ? sfx[tid + off] : 0u;
        __syncthreads();
        sfx[tid] = v + add;
        __syncthreads();
    }
    unsigned int above = (tid < 1023) ? sfx[tid + 1] : 0u;
    if (sfx[tid] >= TOPK && above < TOPK) {
        unsigned int cum = above;
        for (int v = c0 + 63; v >= c0; v--) {
            cum += h[v];
            if (cum >= TOPK) { g_thresh[b] = v; break; }
        }
    }
    __syncthreads();
    {
        uint4* h4 = (uint4*)(h + c0);
        uint4 z = make_uint4(0u, 0u, 0u, 0u);
#pragma unroll
        for (int j = 0; j < 16; j++) h4[j] = z;   // self-reset
    }
}

__global__ void collect_kernel() {
    const int b = blockIdx.x;
    int t16 = g_thresh[b];
    const unsigned int v16 = (unsigned int)(t16 > BAND ? t16 - BAND : 0);
    const float* sc = g_score + (size_t)b * NPTS;
    const int base = blockIdx.y * (NPTS / 16);
    for (int i = threadIdx.x; i < NPTS / 16; i += 1024) {
        int gi = base + i;
        if ((fkey(sc[gi]) >> 16) >= v16) {
            int p = atomicAdd(&g_cnt[b], 1);
            if (p < CAP) g_candidx[(size_t)b * CAP + p] = gi;
        }
    }
}

// ================= exact rescore + full rows (bit-identical chains) ==========
// Score key: frozen sliced FC2 order (chunk-4/period-16, ((s0+s1)+s2)+s3).
// Full 8-ch rows: sequential hh chain per output (verified passing order).
__global__ void __launch_bounds__(256)
exact_kernel(const float* __restrict__ feat, const float* __restrict__ W1,
             const float* __restrict__ b1, const float* __restrict__ W2,
             const float* __restrict__ b2) {
    __shared__ float fcol[CH][16];
    __shared__ float hs[HID][16];
    __shared__ float w2s7[256];
    __shared__ float w2full[HID * OUTC];
    __shared__ float b2s[OUTC];
    __shared__ float ps[64];
    __shared__ int nidx[16];

    const int tid = threadIdx.x;
    const int b = blockIdx.x;
    const int cnt0 = g_cnt[b];
    const int cnt = cnt0 < CAP ? cnt0 : CAP;
    const float b27 = b2[7];

    w2s7[tid] = W2[tid * OUTC + 7];
    for (int i = tid; i < HID * OUTC; i += 256) w2full[i] = W2[i];
    if (tid < OUTC) b2s[tid] = b2[tid];

    for (int base = blockIdx.y * 16; base < cnt; base += gridDim.y * 16) {
        const int m = (cnt - base) < 16 ? (cnt - base) : 16;
        __syncthreads();
        if (tid < 16)
            nidx[tid] = g_candidx[(size_t)b * CAP + base + (tid < m ? tid : 0)];
        __syncthreads();

#pragma unroll
        for (int p = 0; p < 16; p++)
            fcol[tid][p] = feat[((size_t)b * CH + tid) * NPTS + nidx[p]];
        __syncthreads();

        float acc[16];
#pragma unroll
        for (int p = 0; p < 16; p++) acc[p] = 0.0f;
#pragma unroll 4
        for (int c = 0; c < CH; c++) {
            float w = W1[(size_t)c * HID + tid];
#pragma unroll
            for (int p = 0; p < 16; p++) acc[p] = fmaf(fcol[c][p], w, acc[p]);
        }
        float b1v = b1[tid];
#pragma unroll
        for (int p = 0; p < 16; p++) hs[tid][p] = fmaxf(acc[p] + b1v, 0.0f);
        __syncthreads();

        // sliced score partials (frozen order)
        if (tid < 64) {
            const int pt = tid >> 2, z = tid & 3;
            float a = 0.0f;
#pragma unroll
            for (int i = 0; i < 16; i++) {
                int kb = 16 * i + 4 * z;
#pragma unroll
                for (int kk = 0; kk < 4; kk++)
                    a = fmaf(hs[kb + kk][pt], w2s7[kb + kk], a);
            }
            ps[pt * 4 + z] = a;
        }
        // full 8-channel output rows (sequential chains)
        if (tid >= 128) {
            int p = (tid - 128) >> 3, o = (tid - 128) & 7;
            if (p < m) {
                float a = 0.0f;
#pragma unroll 16
                for (int hh = 0; hh < HID; hh++)
                    a = fmaf(hs[hh][p], w2full[hh * OUTC + o], a);
                g_rows[((size_t)b * CAP + base + p) * OUTC + o] = a + b2s[o];
            }
        }
        __syncthreads();

        if (tid < m) {
            float sc = ((ps[tid * 4 + 0] + ps[tid * 4 + 1]) + ps[tid * 4 + 2]) + ps[tid * 4 + 3];
            sc += b27;
            g_cand[(size_t)b * CAP + base + tid] =
                ((unsigned long long)fkey(sc) << 32) |
                (unsigned long long)(0xFFFFFFFFu - (unsigned int)nidx[tid]);
        }
    }
}

// ================= sort candidates (with slot payload), write output =========
#define SORT_SMEM (CAP * 8 + CAP * 4)
__global__ void sort_out_kernel(float* __restrict__ out) {
    extern __shared__ char ssm[];
    unsigned long long* cand = (unsigned long long*)ssm;   // CAP
    int* slot = (int*)(ssm + CAP * 8);                      // CAP
    __shared__ int s_m;
    const int b = blockIdx.x;
    const int tid = threadIdx.x;

    const int M0 = g_cnt[b];
    const int M = M0 < CAP ? M0 : CAP;
    if (tid == 0) {
        int m = 1024;
        while (m < M) m <<= 1;
        s_m = m;
    }
    __syncthreads();
    const int m = s_m;

    for (int i = tid; i < m; i += 1024) {
        cand[i] = (i < M) ? g_cand[(size_t)b * CAP + i] : 0ULL;
        slot[i] = i;
    }
    __syncthreads();

    for (unsigned int k = 2; k <= (unsigned int)m; k <<= 1) {
        for (unsigned int j = k >> 1; j > 0; j >>= 1) {
            for (unsigned int i = tid; i < (unsigned int)m; i += 1024) {
                unsigned int ixj = i ^ j;
                if (ixj > i) {
                    unsigned long long a = cand[i], c2 = cand[ixj];
                    bool up = ((i & k) == 0);
                    if ((a > c2) == up) {
                        cand[i] = c2; cand[ixj] = a;
                        int t = slot[i]; slot[i] = slot[ixj]; slot[ixj] = t;
                    }
                }
            }
            __syncthreads();
        }
    }
    if (tid < TOPK) {
        int s = slot[m - 1 - tid];
        const float* row = &g_rows[((size_t)b * CAP + s) * OUTC];
        float4 r0 = *(const float4*)row;
        float4 r1 = *(const float4*)(row + 4);
        float* op = out + ((size_t)(b * TOPK + tid)) * OUTC;
        *(float4*)op = r0;
        *(float4*)(op + 4) = r1;
    }
    if (tid == 0) g_cnt[b] = 0;   // self-reset
}

// ---------------- launch ----------------
extern "C" void kernel_launch(void* const* d_in, const int* in_sizes, int n_in,
                              void* d_out, int out_size) {
    // inputs: 0 points(unused), 1 features, 2 W1, 3 b1, 4 W2, 5 b2, 6 topk
    const float* feat = (const float*)d_in[1];
    const float* W1 = (const float*)d_in[2];
    const float* b1 = (const float*)d_in[3];
    const float* W2 = (const float*)d_in[4];
    const float* b2 = (const float*)d_in[5];
    float* out = (float*)d_out;

    cudaFuncSetAttribute(approx_score_kernel,
                         cudaFuncAttributeMaxDynamicSharedMemorySize, ASMEM);
    cudaFuncSetAttribute(sort_out_kernel,
                         cudaFuncAttributeMaxDynamicSharedMemorySize, SORT_SMEM);

    w1f8_kernel<<<64, 1024>>>(W1);
    approx_score_kernel<<<dim3(NPTS / BM, BATCH), 256, ASMEM>>>(feat, b1, W2, b2);
    thresh_kernel<<<BATCH, 1024>>>();
    collect_kernel<<<dim3(BATCH, 16), 1024>>>();
    exact_kernel<<<dim3(BATCH, 64), 256>>>(feat, W1, b1, W2, b2);
    sort_out_kernel<<<BATCH, 1024, SORT_SMEM>>>(out);
}

// round 14
// speedup vs baseline: 1.4355x; 1.4355x over previous
#include <cuda_runtime.h>
#include <cuda_bf16.h>

// Problem constants (fixed by the dataset)
#define BATCH 8
#define CH    256
#define NPTS  65536
#define HID   256
#define OUTC  8
#define TOPK  512

#define CAP   8192
#define BAND  16       // 16-bit buckets below approx threshold (bf16 model, validated)

// Scratch (no cudaMalloc). Zero-init at load; consumers self-reset for replay.
__device__ float g_score[BATCH * NPTS];
__device__ __align__(16) unsigned int g_hist16[BATCH * 65536];
__device__ int g_candidx[BATCH * CAP];
__device__ unsigned long long g_cand[BATCH * CAP];
__device__ __align__(16) float g_rows[BATCH * CAP * OUTC];   // exact 8-ch rows per candidate
__device__ int g_cnt[BATCH];
__device__ int g_thresh[BATCH];
__device__ __align__(16) __nv_bfloat16 g_w1bf[CH * HID];     // W1 bf16 [k][n]

__device__ __forceinline__ unsigned int fkey(float f) {
    unsigned int u = __float_as_uint(f);
    return (u & 0x80000000u) ? ~u : (u | 0x80000000u);
}

// ---------------- helpers ----------------
__device__ __forceinline__ void cp16(unsigned dst, const void* src) {
    asm volatile("cp.async.cg.shared.global [%0], [%1], 16;" :: "r"(dst), "l"(src));
}
__device__ __forceinline__ void cp_commit() { asm volatile("cp.async.commit_group;"); }
__device__ __forceinline__ void cp_wait0() { asm volatile("cp.async.wait_group 0;"); }

#define LDSM4T(r0, r1, r2, r3, addr)                                          \
    asm volatile("ldmatrix.sync.aligned.m8n8.x4.trans.shared.b16 "            \
                 "{%0,%1,%2,%3}, [%4];"                                       \
                 : "=r"(r0), "=r"(r1), "=r"(r2), "=r"(r3) : "r"(addr))

#define MMA_BF16(c0, c1, c2, c3, a0, a1, a2, a3, b0, b1)                      \
    asm volatile("mma.sync.aligned.m16n8k16.row.col.f32.bf16.bf16.f32 "       \
                 "{%0,%1,%2,%3}, {%4,%5,%6,%7}, {%8,%9}, {%0,%1,%2,%3};"      \
                 : "+f"(c0), "+f"(c1), "+f"(c2), "+f"(c3)                     \
                 : "r"(a0), "r"(a1), "r"(a2), "r"(a3), "r"(b0), "r"(b1))

// ================= W1 -> bf16 [k][n] =========================================
__global__ void w1bf_kernel(const float* __restrict__ W1) {
    int i = blockIdx.x * 1024 + threadIdx.x;
    g_w1bf[i] = __float2bfloat16(W1[i]);
}

// ================= Phase A: approx scores (bf16 MMA, 2 blocks/SM) ============
// Block: 128 points, K=256, HID in 4 chunks of 64. fB 68 KB + single-buffered
// W1 chunk 36 KB => 106 KB dynamic => 2 CTAs/SM (occupancy experiment).
#define BM      128
#define ROWB_F  136                   // fB row stride (bf16): 128 pts + 8 pad
#define ROWB_W  72                    // w1s row stride: 64 n + 8 pad
#define FB_ELEMS  (256 * ROWB_F)      // 34816
#define W1S_ELEMS (256 * ROWB_W)      // 18432
#define ASMEM   ((FB_ELEMS + W1S_ELEMS) * 2)   // 106496 bytes

__global__ void __launch_bounds__(256, 2)
approx_score_kernel(const float* __restrict__ feat, const float* __restrict__ b1,
                    const float* __restrict__ W2, const float* __restrict__ b2) {
    extern __shared__ __nv_bfloat16 smem[];
    __nv_bfloat16* fB = smem;                       // [256 k][ROWB_F]  natural [c][pt]
    __nv_bfloat16* w1s = smem + FB_ELEMS;           // [256 k][ROWB_W]  natural [k][n]
    __shared__ float b1s[256];
    __shared__ float w27[256];

    const int tid = threadIdx.x;
    const int b = blockIdx.y;
    const int n0 = blockIdx.x * BM;
    const int lane = tid & 31;
    const int warp = tid >> 5;          // 0..7 -> 16 points each
    const int g = lane >> 2;
    const int tg = lane & 3;
    const int P0 = warp * 16;

    // ldmatrix lane address components (validated round 9)
    const int aK = (lane & 7) + ((lane & 16) >> 1);
    const int aP = lane & 8;
    const int bK = lane & 15;
    const int bN = (lane & 16) >> 1;

    const unsigned fB_u = (unsigned)__cvta_generic_to_shared(fB);
    const unsigned w1_u = (unsigned)__cvta_generic_to_shared(w1s);

    b1s[tid] = b1[tid];
    w27[tid] = W2[tid * OUTC + 7];
    const float b27 = b2[7];

    // issue W1 chunk nc into the single buffer (cp.async from bf16 global)
    auto issue = [&](int nc) {
#pragma unroll
        for (int j = 0; j < 8; j++) {
            int idx = j * 256 + tid;        // 0..2047
            int k = idx >> 3;
            int seg = idx & 7;
            cp16(w1_u + (unsigned)((k * ROWB_W + seg * 8) * 2),
                 &g_w1bf[k * HID + nc * 64 + seg * 8]);
        }
        cp_commit();
    };

    issue(0);

    // stage fB: feat [c][n0..n0+127] -> bf16 natural layout (overlaps cp.async)
    const float* fbase = feat + (size_t)b * CH * NPTS + n0;
#pragma unroll 8
    for (int it = 0; it < 32; it++) {
        int idx4 = it * 256 + tid;          // 0..8191
        int c = idx4 >> 5;
        int p4 = (idx4 & 31) << 2;
        float4 v = *(const float4*)&fbase[(size_t)c * NPTS + p4];
        __nv_bfloat162 lo = __floats2bfloat162_rn(v.x, v.y);
        __nv_bfloat162 hi = __floats2bfloat162_rn(v.z, v.w);
        *reinterpret_cast<__nv_bfloat162*>(&fB[c * ROWB_F + p4]) = lo;
        *reinterpret_cast<__nv_bfloat162*>(&fB[c * ROWB_F + p4 + 2]) = hi;
    }

    float sp0 = 0.0f, sp1 = 0.0f;

#pragma unroll 1
    for (int nc = 0; nc < 4; nc++) {
        cp_wait0();
        __syncthreads();    // w1s staged; fB staged (nc=0)

        float c[8][4];
#pragma unroll
        for (int nt = 0; nt < 8; nt++)
#pragma unroll
            for (int j = 0; j < 4; j++) c[nt][j] = 0.0f;

#pragma unroll 4
        for (int kt = 0; kt < 16; kt++) {
            const int k0 = kt * 16;
            unsigned a0, a1, a2, a3;
            LDSM4T(a0, a1, a2, a3,
                   fB_u + (unsigned)(((k0 + aK) * ROWB_F + P0 + aP) * 2));
            unsigned bq[4][4];
#pragma unroll
            for (int bi = 0; bi < 4; bi++)
                LDSM4T(bq[bi][0], bq[bi][1], bq[bi][2], bq[bi][3],
                       w1_u + (unsigned)(((k0 + bK) * ROWB_W + bi * 16 + bN) * 2));
#pragma unroll
            for (int nt = 0; nt < 8; nt++) {
                const int bi = nt >> 1, pr = (nt & 1) * 2;
                MMA_BF16(c[nt][0], c[nt][1], c[nt][2], c[nt][3],
                         a0, a1, a2, a3, bq[bi][pr], bq[bi][pr + 1]);
            }
        }

        // relu + b1 + dot W2[:,7] in-register
#pragma unroll
        for (int nt = 0; nt < 8; nt++) {
            int col = nc * 64 + nt * 8 + 2 * tg;
            float bb0 = b1s[col], bb1 = b1s[col + 1];
            float w0 = w27[col], w1v = w27[col + 1];
            sp0 += fmaxf(c[nt][0] + bb0, 0.0f) * w0 +
                   fmaxf(c[nt][1] + bb1, 0.0f) * w1v;
            sp1 += fmaxf(c[nt][2] + bb0, 0.0f) * w0 +
                   fmaxf(c[nt][3] + bb1, 0.0f) * w1v;
        }

        __syncthreads();    // all warps done reading w1s before refill
        if (nc + 1 < 4) issue(nc + 1);
    }

    // quad-reduce over tg (disjoint hid columns)
    sp0 += __shfl_xor_sync(0xFFFFFFFFu, sp0, 1);
    sp0 += __shfl_xor_sync(0xFFFFFFFFu, sp0, 2);
    sp1 += __shfl_xor_sync(0xFFFFFFFFu, sp1, 1);
    sp1 += __shfl_xor_sync(0xFFFFFFFFu, sp1, 2);

    if (tg == 0) {
        float s0 = sp0 + b27, s1 = sp1 + b27;
        int pt0 = n0 + P0 + g;
        g_score[(size_t)b * NPTS + pt0] = s0;
        g_score[(size_t)b * NPTS + pt0 + 8] = s1;
        atomicAdd(&g_hist16[(size_t)b * 65536 + (fkey(s0) >> 16)], 1u);
        atomicAdd(&g_hist16[(size_t)b * 65536 + (fkey(s1) >> 16)], 1u);
    }
}

// ================= Phase B: threshold + band collect =========================
__global__ void thresh_kernel() {
    __shared__ unsigned int sfx[1024];
    const int b = blockIdx.x;
    const int tid = threadIdx.x;
    unsigned int* h = g_hist16 + (size_t)b * 65536;
    const int c0 = tid * 64;

    unsigned int s = 0;
    {
        const uint4* h4 = (const uint4*)(h + c0);
#pragma unroll
        for (int j = 0; j < 16; j++) {
            uint4 v = h4[j];
            s += v.x + v.y + v.z + v.w;
        }
    }
    sfx[tid] = s;
    __syncthreads();
    for (int off = 1; off < 1024; off <<= 1) {
        unsigned int v = sfx[tid];
        unsigned int add = (tid + off < 1024) ? sfx[tid + off] : 0u;
        __syncthreads();
        sfx[tid] = v + add;
        __syncthreads();
    }
    unsigned int above = (tid < 1023) ? sfx[tid + 1] : 0u;
    if (sfx[tid] >= TOPK && above < TOPK) {
        unsigned int cum = above;
        for (int v = c0 + 63; v >= c0; v--) {
            cum += h[v];
            if (cum >= TOPK) { g_thresh[b] = v; break; }
        }
    }
    __syncthreads();
    {
        uint4* h4 = (uint4*)(h + c0);
        uint4 z = make_uint4(0u, 0u, 0u, 0u);
#pragma unroll
        for (int j = 0; j < 16; j++) h4[j] = z;   // self-reset
    }
}

__global__ void collect_kernel() {
    const int b = blockIdx.x;
    int t16 = g_thresh[b];
    const unsigned int v16 = (unsigned int)(t16 > BAND ? t16 - BAND : 0);
    const float* sc = g_score + (size_t)b * NPTS;
    const int base = blockIdx.y * (NPTS / 16);
    for (int i = threadIdx.x; i < NPTS / 16; i += 1024) {
        int gi = base + i;
        if ((fkey(sc[gi]) >> 16) >= v16) {
            int p = atomicAdd(&g_cnt[b], 1);
            if (p < CAP) g_candidx[(size_t)b * CAP + p] = gi;
        }
    }
}

// ================= exact rescore + full rows (bit-identical chains) ==========
// Score key: frozen sliced FC2 order (chunk-4/period-16, ((s0+s1)+s2)+s3).
// Full 8-ch rows: sequential hh chain per output (verified passing order).
__global__ void __launch_bounds__(256)
exact_kernel(const float* __restrict__ feat, const float* __restrict__ W1,
             const float* __restrict__ b1, const float* __restrict__ W2,
             const float* __restrict__ b2) {
    __shared__ float fcol[CH][16];
    __shared__ float hs[HID][16];
    __shared__ float w2s7[256];
    __shared__ float w2full[HID * OUTC];
    __shared__ float b2s[OUTC];
    __shared__ float ps[64];
    __shared__ int nidx[16];

    const int tid = threadIdx.x;
    const int b = blockIdx.x;
    const int cnt0 = g_cnt[b];
    const int cnt = cnt0 < CAP ? cnt0 : CAP;
    const float b27 = b2[7];

    w2s7[tid] = W2[tid * OUTC + 7];
    for (int i = tid; i < HID * OUTC; i += 256) w2full[i] = W2[i];
    if (tid < OUTC) b2s[tid] = b2[tid];

    for (int base = blockIdx.y * 16; base < cnt; base += gridDim.y * 16) {
        const int m = (cnt - base) < 16 ? (cnt - base) : 16;
        __syncthreads();
        if (tid < 16)
            nidx[tid] = g_candidx[(size_t)b * CAP + base + (tid < m ? tid : 0)];
        __syncthreads();

#pragma unroll
        for (int p = 0; p < 16; p++)
            fcol[tid][p] = feat[((size_t)b * CH + tid) * NPTS + nidx[p]];
        __syncthreads();

        float acc[16];
#pragma unroll
        for (int p = 0; p < 16; p++) acc[p] = 0.0f;
#pragma unroll 4
        for (int c = 0; c < CH; c++) {
            float w = W1[(size_t)c * HID + tid];
#pragma unroll
            for (int p = 0; p < 16; p++) acc[p] = fmaf(fcol[c][p], w, acc[p]);
        }
        float b1v = b1[tid];
#pragma unroll
        for (int p = 0; p < 16; p++) hs[tid][p] = fmaxf(acc[p] + b1v, 0.0f);
        __syncthreads();

        // sliced score partials (frozen order)
        if (tid < 64) {
            const int pt = tid >> 2, z = tid & 3;
            float a = 0.0f;
#pragma unroll
            for (int i = 0; i < 16; i++) {
                int kb = 16 * i + 4 * z;
#pragma unroll
                for (int kk = 0; kk < 4; kk++)
                    a = fmaf(hs[kb + kk][pt], w2s7[kb + kk], a);
            }
            ps[pt * 4 + z] = a;
        }
        // full 8-channel output rows (sequential chains)
        if (tid >= 128) {
            int p = (tid - 128) >> 3, o = (tid - 128) & 7;
            if (p < m) {
                float a = 0.0f;
#pragma unroll 16
                for (int hh = 0; hh < HID; hh++)
                    a = fmaf(hs[hh][p], w2full[hh * OUTC + o], a);
                g_rows[((size_t)b * CAP + base + p) * OUTC + o] = a + b2s[o];
            }
        }
        __syncthreads();

        if (tid < m) {
            float sc = ((ps[tid * 4 + 0] + ps[tid * 4 + 1]) + ps[tid * 4 + 2]) + ps[tid * 4 + 3];
            sc += b27;
            g_cand[(size_t)b * CAP + base + tid] =
                ((unsigned long long)fkey(sc) << 32) |
                (unsigned long long)(0xFFFFFFFFu - (unsigned int)nidx[tid]);
        }
    }
}

// ================= sort candidates (with slot payload), write output =========
#define SORT_SMEM (CAP * 8 + CAP * 4)
__global__ void sort_out_kernel(float* __restrict__ out) {
    extern __shared__ char ssm[];
    unsigned long long* cand = (unsigned long long*)ssm;   // CAP
    int* slot = (int*)(ssm + CAP * 8);                      // CAP
    __shared__ int s_m;
    const int b = blockIdx.x;
    const int tid = threadIdx.x;

    const int M0 = g_cnt[b];
    const int M = M0 < CAP ? M0 : CAP;
    if (tid == 0) {
        int m = 1024;
        while (m < M) m <<= 1;
        s_m = m;
    }
    __syncthreads();
    const int m = s_m;

    for (int i = tid; i < m; i += 1024) {
        cand[i] = (i < M) ? g_cand[(size_t)b * CAP + i] : 0ULL;
        slot[i] = i;
    }
    __syncthreads();

    for (unsigned int k = 2; k <= (unsigned int)m; k <<= 1) {
        for (unsigned int j = k >> 1; j > 0; j >>= 1) {
            for (unsigned int i = tid; i < (unsigned int)m; i += 1024) {
                unsigned int ixj = i ^ j;
                if (ixj > i) {
                    unsigned long long a = cand[i], c2 = cand[ixj];
                    bool up = ((i & k) == 0);
                    if ((a > c2) == up) {
                        cand[i] = c2; cand[ixj] = a;
                        int t = slot[i]; slot[i] = slot[ixj]; slot[ixj] = t;
                    }
                }
            }
            __syncthreads();
        }
    }
    if (tid < TOPK) {
        int s = slot[m - 1 - tid];
        const float* row = &g_rows[((size_t)b * CAP + s) * OUTC];
        float4 r0 = *(const float4*)row;
        float4 r1 = *(const float4*)(row + 4);
        float* op = out + ((size_t)(b * TOPK + tid)) * OUTC;
        *(float4*)op = r0;
        *(float4*)(op + 4) = r1;
    }
    if (tid == 0) g_cnt[b] = 0;   // self-reset
}

// ---------------- launch ----------------
extern "C" void kernel_launch(void* const* d_in, const int* in_sizes, int n_in,
                              void* d_out, int out_size) {
    // inputs: 0 points(unused), 1 features, 2 W1, 3 b1, 4 W2, 5 b2, 6 topk
    const float* feat = (const float*)d_in[1];
    const float* W1 = (const float*)d_in[2];
    const float* b1 = (const float*)d_in[3];
    const float* W2 = (const float*)d_in[4];
    const float* b2 = (const float*)d_in[5];
    float* out = (float*)d_out;

    cudaFuncSetAttribute(approx_score_kernel,
                         cudaFuncAttributeMaxDynamicSharedMemorySize, ASMEM);
    cudaFuncSetAttribute(sort_out_kernel,
                         cudaFuncAttributeMaxDynamicSharedMemorySize, SORT_SMEM);

    w1bf_kernel<<<64, 1024>>>(W1);
    approx_score_kernel<<<dim3(NPTS / BM, BATCH), 256, ASMEM>>>(feat, b1, W2, b2);
    thresh_kernel<<<BATCH, 1024>>>();
    collect_kernel<<<dim3(BATCH, 16), 1024>>>();
    exact_kernel<<<dim3(BATCH, 64), 256>>>(feat, W1, b1, W2, b2);
    sort_out_kernel<<<BATCH, 1024, SORT_SMEM>>>(out);
}